// round 7
// baseline (speedup 1.0000x reference)
#include <cuda_runtime.h>
#include <cuda_bf16.h>
#include <math.h>

// Problem constants (fixed by the dataset)
#define BB   64
#define HH   1024
#define VV   32000
#define DEPTHN 5
#define LEAVES 32            // 2^DEPTH
#define MAXROWS (BB*LEAVES)  // 2048
#define GH_LD (6*HH)         // 6144 : [l gates 3H | r gates 3H]

// ---------------- device scratch (static, no runtime alloc) ----------------
__device__ float            g_curA[MAXROWS*HH];
__device__ float            g_curB[MAXROWS*HH];
__device__ __nv_bfloat16    g_curbf[MAXROWS*HH];
__device__ float            g_gh[(MAXROWS/2)*GH_LD];        // max 1024 rows * 6144
__device__ __nv_bfloat16    g_wcat[GH_LD*HH];               // [Whh_l ; Whh_r] (6144 x 1024)
__device__ __nv_bfloat16    g_wout[(size_t)VV*HH];          // 32000 x 1024
__device__ float            g_lse[MAXROWS];

// ---------------- helpers ----------------
__device__ __forceinline__ float sigmoidf_(float x) { return 1.f / (1.f + __expf(-x)); }

__device__ __forceinline__ void mma16816(float* c, const unsigned* a, const unsigned* b) {
    asm volatile(
        "mma.sync.aligned.m16n8k16.row.col.f32.bf16.bf16.f32 "
        "{%0,%1,%2,%3}, {%4,%5,%6,%7}, {%8,%9}, {%0,%1,%2,%3};\n"
        : "+f"(c[0]), "+f"(c[1]), "+f"(c[2]), "+f"(c[3])
        : "r"(a[0]), "r"(a[1]), "r"(a[2]), "r"(a[3]), "r"(b[0]), "r"(b[1]));
}

// ---------------- fp32 -> bf16 conversion ----------------
__global__ void f2bf_kernel(const float* __restrict__ src, __nv_bfloat16* __restrict__ dst, int n2) {
    int i = blockIdx.x * blockDim.x + threadIdx.x;
    if (i < n2) {
        float2 v = reinterpret_cast<const float2*>(src)[i];
        reinterpret_cast<__nv_bfloat162*>(dst)[i] = __float22bfloat162_rn(v);
    }
}

// ---------------- init: encoding -> curA (fp32) + curbf ----------------
__global__ void init_kernel(const float* __restrict__ enc, float* __restrict__ cur,
                            __nv_bfloat16* __restrict__ curbf) {
    int i = blockIdx.x * blockDim.x + threadIdx.x;   // 64*1024 = 65536 total
    float v = enc[i];
    cur[i]   = v;
    curbf[i] = __float2bfloat16(v);
}

// ---------------- bf16 GEMM:  C[M,N] = A[M,K] @ B[N,K]^T (+bias)  ----------------
// K = 1024 fixed. BM=128, BN=64, BK=32, 256 threads, warp tile 32x32 (2x4 m16n8k16).
#define BM 128
#define BN 64
#define BK 32
#define AST 48   // smem row stride (bf16) — 96B, keeps uint4 alignment
#define BST 48

__global__ void __launch_bounds__(256)
gemm_bf16_kernel(const __nv_bfloat16* __restrict__ A,
                 const __nv_bfloat16* __restrict__ B,
                 float* __restrict__ C,
                 const float* __restrict__ bias,
                 int M, int ldc)
{
    __shared__ __nv_bfloat16 As[BM * AST];
    __shared__ __nv_bfloat16 Bs[BN * BST];

    const int tid  = threadIdx.x;
    const int warp = tid >> 5;
    const int lane = tid & 31;
    const int wm   = warp >> 1;      // 0..3  (m)
    const int wn   = warp & 1;       // 0..1  (n)
    const int g    = lane >> 2;      // groupID 0..7
    const int ti   = lane & 3;       // thread-in-group 0..3
    const int rowBase = blockIdx.y * BM;
    const int colBase = blockIdx.x * BN;

    float acc[2][4][4];
    #pragma unroll
    for (int mt = 0; mt < 2; mt++)
        #pragma unroll
        for (int nt = 0; nt < 4; nt++)
            #pragma unroll
            for (int q = 0; q < 4; q++) acc[mt][nt][q] = 0.f;

    for (int k0 = 0; k0 < HH; k0 += BK) {
        // ---- global -> shared: A tile 128x32 (2 uint4/thread), B tile 64x32 (1 uint4/thread)
        #pragma unroll
        for (int i = 0; i < 2; i++) {
            int idx = tid + i * 256;              // 0..511
            int r   = idx >> 2;                   // 0..127
            int c8  = (idx & 3) << 3;             // 0,8,16,24
            uint4 v = make_uint4(0u, 0u, 0u, 0u);
            if (rowBase + r < M)
                v = *reinterpret_cast<const uint4*>(A + (size_t)(rowBase + r) * HH + k0 + c8);
            *reinterpret_cast<uint4*>(&As[r * AST + c8]) = v;
        }
        {
            int r  = tid >> 2;                    // 0..63
            int c8 = (tid & 3) << 3;
            uint4 v = *reinterpret_cast<const uint4*>(B + (size_t)(colBase + r) * HH + k0 + c8);
            *reinterpret_cast<uint4*>(&Bs[r * BST + c8]) = v;
        }
        __syncthreads();

        #pragma unroll
        for (int kk = 0; kk < BK; kk += 16) {
            unsigned a[2][4], b[4][2];
            #pragma unroll
            for (int mt = 0; mt < 2; mt++) {
                int r0 = wm * 32 + mt * 16 + g;
                const __nv_bfloat16* p = &As[r0 * AST + kk + 2 * ti];
                a[mt][0] = *reinterpret_cast<const unsigned*>(p);
                a[mt][1] = *reinterpret_cast<const unsigned*>(p + 8 * AST);
                a[mt][2] = *reinterpret_cast<const unsigned*>(p + 8);
                a[mt][3] = *reinterpret_cast<const unsigned*>(p + 8 * AST + 8);
            }
            #pragma unroll
            for (int nt = 0; nt < 4; nt++) {
                int c0 = wn * 32 + nt * 8 + g;
                const __nv_bfloat16* p = &Bs[c0 * BST + kk + 2 * ti];
                b[nt][0] = *reinterpret_cast<const unsigned*>(p);
                b[nt][1] = *reinterpret_cast<const unsigned*>(p + 8);
            }
            #pragma unroll
            for (int mt = 0; mt < 2; mt++)
                #pragma unroll
                for (int nt = 0; nt < 4; nt++)
                    mma16816(acc[mt][nt], a[mt], b[nt]);
        }
        __syncthreads();
    }

    // ---- epilogue
    #pragma unroll
    for (int mt = 0; mt < 2; mt++) {
        int r0 = rowBase + wm * 32 + mt * 16 + g;
        #pragma unroll
        for (int nt = 0; nt < 4; nt++) {
            int c = colBase + wn * 32 + nt * 8 + 2 * ti;
            float b0 = bias ? bias[c]     : 0.f;
            float b1 = bias ? bias[c + 1] : 0.f;
            if (r0 < M) {
                C[(size_t)r0 * ldc + c]     = acc[mt][nt][0] + b0;
                C[(size_t)r0 * ldc + c + 1] = acc[mt][nt][1] + b1;
            }
            if (r0 + 8 < M) {
                C[(size_t)(r0 + 8) * ldc + c]     = acc[mt][nt][2] + b0;
                C[(size_t)(r0 + 8) * ldc + c + 1] = acc[mt][nt][3] + b1;
            }
        }
    }
}

// ---------------- GRU gates: consume gh (raw h@W^T), produce both children ----------------
__global__ void gru_gate_kernel(const float* __restrict__ cur,
                                const float* __restrict__ gh,
                                const float* __restrict__ bih_l, const float* __restrict__ bhh_l,
                                const float* __restrict__ bih_r, const float* __restrict__ bhh_r,
                                float* __restrict__ nxt, __nv_bfloat16* __restrict__ nxtbf)
{
    int row = blockIdx.x;
    const float* gp = gh  + (size_t)row * GH_LD;
    const float* hp = cur + (size_t)row * HH;
    size_t lo = (size_t)(2 * row) * HH;

    for (int j = threadIdx.x; j < HH; j += blockDim.x) {
        float hv = hp[j];
        // left GRU
        float g0 = gp[j], g1 = gp[HH + j], g2 = gp[2 * HH + j];
        float r  = sigmoidf_(bih_l[j]        + bhh_l[j]        + g0);
        float z  = sigmoidf_(bih_l[HH + j]   + bhh_l[HH + j]   + g1);
        float n  = tanhf   (bih_l[2*HH + j]  + r * (g2 + bhh_l[2*HH + j]));
        float left = (1.f - z) * n + z * hv;
        // right GRU
        g0 = gp[3*HH + j]; g1 = gp[4*HH + j]; g2 = gp[5*HH + j];
        float r2 = sigmoidf_(bih_r[j]        + bhh_r[j]        + g0);
        float z2 = sigmoidf_(bih_r[HH + j]   + bhh_r[HH + j]   + g1);
        float n2 = tanhf   (bih_r[2*HH + j]  + r2 * (g2 + bhh_r[2*HH + j]));
        float right = (1.f - z2) * n2 + z2 * hv;

        nxt[lo + j]        = left;
        nxt[lo + HH + j]   = right;
        nxtbf[lo + j]      = __float2bfloat16(left);
        nxtbf[lo + HH + j] = __float2bfloat16(right);
    }
}

// ---------------- streaming log-sum-exp per row (V=32000) ----------------
__global__ void lse_kernel(const float* __restrict__ logits, float* __restrict__ lse) {
    int row = blockIdx.x;
    const float4* p = reinterpret_cast<const float4*>(logits + (size_t)row * VV);
    float m = -INFINITY, s = 0.f;
    for (int i = threadIdx.x; i < VV / 4; i += blockDim.x) {
        float4 v = p[i];
        float x;
        x = v.x; if (x > m) { s *= __expf(m - x); m = x; } s += __expf(x - m);
        x = v.y; if (x > m) { s *= __expf(m - x); m = x; } s += __expf(x - m);
        x = v.z; if (x > m) { s *= __expf(m - x); m = x; } s += __expf(x - m);
        x = v.w; if (x > m) { s *= __expf(m - x); m = x; } s += __expf(x - m);
    }
    __shared__ float sm[256], ss[256];
    sm[threadIdx.x] = m; ss[threadIdx.x] = s;
    __syncthreads();
    for (int o = 128; o > 0; o >>= 1) {
        if (threadIdx.x < o) {
            float m2 = sm[threadIdx.x + o], s2 = ss[threadIdx.x + o];
            float M = fmaxf(sm[threadIdx.x], m2);
            ss[threadIdx.x] = ss[threadIdx.x] * __expf(sm[threadIdx.x] - M) + s2 * __expf(m2 - M);
            sm[threadIdx.x] = M;
        }
        __syncthreads();
    }
    if (threadIdx.x == 0) lse[row] = sm[0] + __logf(ss[0]);
}

__global__ void norm_kernel(float* __restrict__ logits, const float* __restrict__ lse) {
    int row = blockIdx.x;
    float l = lse[row];
    float4* p = reinterpret_cast<float4*>(logits + (size_t)row * VV);
    for (int i = threadIdx.x; i < VV / 4; i += blockDim.x) {
        float4 v = p[i];
        v.x -= l; v.y -= l; v.z -= l; v.w -= l;
        p[i] = v;
    }
}

// ---------------- launch ----------------
extern "C" void kernel_launch(void* const* d_in, const int* in_sizes, int n_in,
                              void* d_out, int out_size) {
    const float* enc   = (const float*)d_in[0];
    const float* Whh_l = (const float*)d_in[1];
    const float* bih_l = (const float*)d_in[2];
    const float* bhh_l = (const float*)d_in[3];
    const float* Whh_r = (const float*)d_in[4];
    const float* bih_r = (const float*)d_in[5];
    const float* bhh_r = (const float*)d_in[6];
    const float* W_out = (const float*)d_in[7];
    const float* b_out = (const float*)d_in[8];
    float* out = (float*)d_out;

    float *p_curA, *p_curB, *p_gh, *p_lse;
    __nv_bfloat16 *p_curbf, *p_wcat, *p_wout;
    cudaGetSymbolAddress((void**)&p_curA,  g_curA);
    cudaGetSymbolAddress((void**)&p_curB,  g_curB);
    cudaGetSymbolAddress((void**)&p_gh,    g_gh);
    cudaGetSymbolAddress((void**)&p_lse,   g_lse);
    cudaGetSymbolAddress((void**)&p_curbf, g_curbf);
    cudaGetSymbolAddress((void**)&p_wcat,  g_wcat);
    cudaGetSymbolAddress((void**)&p_wout,  g_wout);

    // weight conversions (every call — deterministic)
    {
        int nW = 3 * HH * HH;             // 3,145,728 per GRU weight
        int n2 = nW / 2;
        f2bf_kernel<<<(n2 + 255) / 256, 256>>>(Whh_l, p_wcat, n2);
        f2bf_kernel<<<(n2 + 255) / 256, 256>>>(Whh_r, p_wcat + nW, n2);
        int n2o = (VV * HH) / 2;          // 16,384,000
        f2bf_kernel<<<(n2o + 255) / 256, 256>>>(W_out, p_wout, n2o);
    }

    // level 0 input
    init_kernel<<<(BB * HH) / 256, 256>>>(enc, p_curA, p_curbf);

    // tree expansion
    float* cur = p_curA;
    float* nxt = p_curB;
    for (int level = 0; level < DEPTHN; level++) {
        int rows = BB << level;                               // 64..1024
        dim3 grid(GH_LD / BN, (rows + BM - 1) / BM);
        gemm_bf16_kernel<<<grid, 256>>>(p_curbf, p_wcat, p_gh, nullptr, rows, GH_LD);
        gru_gate_kernel<<<rows, 256>>>(cur, p_gh, bih_l, bhh_l, bih_r, bhh_r, nxt, p_curbf);
        float* t = cur; cur = nxt; nxt = t;
    }

    // output projection: logits (+bias) straight into d_out
    {
        dim3 grid(VV / BN, MAXROWS / BM);                     // (500, 16)
        gemm_bf16_kernel<<<grid, 256>>>(p_curbf, p_wout, out, b_out, MAXROWS, VV);
    }

    // log_softmax
    lse_kernel<<<MAXROWS, 256>>>(out, p_lse);
    norm_kernel<<<MAXROWS, 256>>>(out, p_lse);
}

// round 8
// speedup vs baseline: 1.5684x; 1.5684x over previous
#include <cuda_runtime.h>
#include <cuda_bf16.h>
#include <math.h>

// Problem constants (fixed by the dataset)
#define BB   64
#define HH   1024
#define VV   32000
#define DEPTHN 5
#define LEAVES 32            // 2^DEPTH
#define MAXROWS (BB*LEAVES)  // 2048
#define GH_LD (6*HH)         // 6144 : [l gates 3H | r gates 3H]

// ---------------- device scratch (static, no runtime alloc) ----------------
__device__ float            g_curA[MAXROWS*HH];
__device__ float            g_curB[MAXROWS*HH];
__device__ __nv_bfloat16    g_curbf[MAXROWS*HH];
__device__ float            g_gh[(MAXROWS/2)*GH_LD];        // max 1024 rows * 6144
__device__ __nv_bfloat16    g_wcat[GH_LD*HH];               // [Whh_l ; Whh_r] (6144 x 1024)
__device__ __nv_bfloat16    g_wout[(size_t)VV*HH];          // 32000 x 1024
__device__ float            g_lse[MAXROWS];

// ---------------- helpers ----------------
__device__ __forceinline__ float sigmoidf_(float x) { return 1.f / (1.f + __expf(-x)); }

__device__ __forceinline__ void mma16816(float* c, const unsigned* a, const unsigned* b) {
    asm volatile(
        "mma.sync.aligned.m16n8k16.row.col.f32.bf16.bf16.f32 "
        "{%0,%1,%2,%3}, {%4,%5,%6,%7}, {%8,%9}, {%0,%1,%2,%3};\n"
        : "+f"(c[0]), "+f"(c[1]), "+f"(c[2]), "+f"(c[3])
        : "r"(a[0]), "r"(a[1]), "r"(a[2]), "r"(a[3]), "r"(b[0]), "r"(b[1]));
}

__device__ __forceinline__ void ldsm_x4(unsigned& r0, unsigned& r1, unsigned& r2, unsigned& r3,
                                        unsigned addr) {
    asm volatile("ldmatrix.sync.aligned.m8n8.x4.shared.b16 {%0,%1,%2,%3}, [%4];\n"
                 : "=r"(r0), "=r"(r1), "=r"(r2), "=r"(r3) : "r"(addr));
}

__device__ __forceinline__ void cp16(unsigned dst, const void* src, int szbytes) {
    asm volatile("cp.async.cg.shared.global [%0], [%1], 16, %2;\n"
                 :: "r"(dst), "l"(src), "r"(szbytes));
}
#define CP_COMMIT() asm volatile("cp.async.commit_group;\n" ::: "memory")
#define CP_WAIT(n)  asm volatile("cp.async.wait_group %0;\n" :: "n"(n) : "memory")

// ---------------- fp32 -> bf16 conversion ----------------
__global__ void f2bf_kernel(const float* __restrict__ src, __nv_bfloat16* __restrict__ dst, int n2) {
    int i = blockIdx.x * blockDim.x + threadIdx.x;
    if (i < n2) {
        float2 v = reinterpret_cast<const float2*>(src)[i];
        reinterpret_cast<__nv_bfloat162*>(dst)[i] = __float22bfloat162_rn(v);
    }
}

// ---------------- init: encoding -> curA (fp32) + curbf ----------------
__global__ void init_kernel(const float* __restrict__ enc, float* __restrict__ cur,
                            __nv_bfloat16* __restrict__ curbf) {
    int i = blockIdx.x * blockDim.x + threadIdx.x;   // 64*1024 total
    float v = enc[i];
    cur[i]   = v;
    curbf[i] = __float2bfloat16(v);
}

// ---------------- pipelined bf16 GEMM:  C[M,N] = A[M,K] @ B[N,K]^T (+bias) ----------------
// K = 1024 fixed. BM=128, BN=128, BK=32, 2-stage cp.async, ldmatrix fragments.
// 256 threads, warp grid 4x2 (m x n), warp tile 32x64 -> 2x8 m16n8k16.
#define BM 128
#define BN 128
#define BK 32
#define KST 40                         // smem row stride in bf16 (80 B, conflict-free for ldmatrix)
#define ASTB (BM*KST*2)                // bytes per A stage (10240)
#define BSTB (BN*KST*2)                // bytes per B stage (10240)

__device__ __forceinline__ void stage_load(const __nv_bfloat16* __restrict__ A,
                                           const __nv_bfloat16* __restrict__ B,
                                           unsigned aS, unsigned bS,
                                           int rowBase, int M, int k0, int tid) {
    // A tile: 128x32 bf16 = 512 x 16B chunks, 2 per thread
    #pragma unroll
    for (int i = 0; i < 2; i++) {
        int c  = tid + i * 256;
        int r  = c >> 2;
        int cc = (c & 3) << 3;                       // bf16 col: 0,8,16,24
        const __nv_bfloat16* src = A + (size_t)(rowBase + r) * HH + k0 + cc;
        int sz = (rowBase + r < M) ? 16 : 0;         // zero-fill OOB rows
        cp16(aS + r * 80 + cc * 2, src, sz);
    }
    // B tile: 128x32, always in-range (N multiple of 128)
    #pragma unroll
    for (int i = 0; i < 2; i++) {
        int c  = tid + i * 256;
        int r  = c >> 2;
        int cc = (c & 3) << 3;
        const __nv_bfloat16* src = B + (size_t)r * HH + k0 + cc;   // B pre-offset by colBase
        cp16(bS + r * 80 + cc * 2, src, 16);
    }
}

__global__ void __launch_bounds__(256, 2)
gemm_bf16_pipe(const __nv_bfloat16* __restrict__ A,
               const __nv_bfloat16* __restrict__ B,
               float* __restrict__ C,
               const float* __restrict__ bias,
               int M, int ldc)
{
    __shared__ __nv_bfloat16 As[2][BM * KST];
    __shared__ __nv_bfloat16 Bs[2][BN * KST];

    const int tid  = threadIdx.x;
    const int warp = tid >> 5;
    const int lane = tid & 31;
    const int wm   = warp >> 1;      // 0..3  (m)
    const int wn   = warp & 1;       // 0..1  (n)
    const int ti   = lane & 3;
    const int g    = lane >> 2;
    const int rowBase = blockIdx.y * BM;
    const int colBase = blockIdx.x * BN;

    const __nv_bfloat16* Bp = B + (size_t)colBase * HH;

    unsigned aB0 = (unsigned)__cvta_generic_to_shared(&As[0][0]);
    unsigned bB0 = (unsigned)__cvta_generic_to_shared(&Bs[0][0]);

    float acc[2][8][4];
    #pragma unroll
    for (int mt = 0; mt < 2; mt++)
        #pragma unroll
        for (int nt = 0; nt < 8; nt++)
            #pragma unroll
            for (int q = 0; q < 4; q++) acc[mt][nt][q] = 0.f;

    const int NK = HH / BK;          // 32

    stage_load(A, Bp, aB0, bB0, rowBase, M, 0, tid);
    CP_COMMIT();

    // Precompute per-lane ldmatrix address offsets (within a stage)
    const int aRowSel = lane & 15;               // row within 16
    const int aColSel = (lane >> 4) << 3;        // 0 or 8
    const int bRowSel = (lane & 7) + (((lane >> 4) & 1) << 3);  // row within 16
    const int bColSel = ((lane >> 3) & 1) << 3;  // 0 or 8

    for (int it = 0; it < NK; it++) {
        if (it + 1 < NK) {
            int s = (it + 1) & 1;
            stage_load(A, Bp, aB0 + s * ASTB, bB0 + s * BSTB, rowBase, M, (it + 1) * BK, tid);
            CP_COMMIT();
            CP_WAIT(1);
        } else {
            CP_WAIT(0);
        }
        __syncthreads();

        const int s = it & 1;
        const unsigned aS = aB0 + s * ASTB;
        const unsigned bS = bB0 + s * BSTB;

        #pragma unroll
        for (int kk = 0; kk < BK; kk += 16) {
            unsigned a[2][4], b[8][2];
            #pragma unroll
            for (int mt = 0; mt < 2; mt++) {
                int row = wm * 32 + mt * 16 + aRowSel;
                ldsm_x4(a[mt][0], a[mt][1], a[mt][2], a[mt][3],
                        aS + row * 80 + (kk + aColSel) * 2);
            }
            #pragma unroll
            for (int p = 0; p < 4; p++) {
                int row = wn * 64 + p * 16 + bRowSel;
                unsigned r0, r1, r2, r3;
                ldsm_x4(r0, r1, r2, r3, bS + row * 80 + (kk + bColSel) * 2);
                b[2*p][0] = r0; b[2*p][1] = r1; b[2*p+1][0] = r2; b[2*p+1][1] = r3;
            }
            #pragma unroll
            for (int mt = 0; mt < 2; mt++)
                #pragma unroll
                for (int nt = 0; nt < 8; nt++)
                    mma16816(acc[mt][nt], a[mt], b[nt]);
        }
        __syncthreads();
    }

    // ---- epilogue
    #pragma unroll
    for (int mt = 0; mt < 2; mt++) {
        int r0 = rowBase + wm * 32 + mt * 16 + g;
        #pragma unroll
        for (int nt = 0; nt < 8; nt++) {
            int c = colBase + wn * 64 + nt * 8 + 2 * ti;
            float b0 = bias ? bias[c]     : 0.f;
            float b1 = bias ? bias[c + 1] : 0.f;
            if (r0 < M) {
                C[(size_t)r0 * ldc + c]     = acc[mt][nt][0] + b0;
                C[(size_t)r0 * ldc + c + 1] = acc[mt][nt][1] + b1;
            }
            if (r0 + 8 < M) {
                C[(size_t)(r0 + 8) * ldc + c]     = acc[mt][nt][2] + b0;
                C[(size_t)(r0 + 8) * ldc + c + 1] = acc[mt][nt][3] + b1;
            }
        }
    }
}

// ---------------- GRU gates: consume gh (raw h@W^T), produce both children ----------------
__global__ void gru_gate_kernel(const float* __restrict__ cur,
                                const float* __restrict__ gh,
                                const float* __restrict__ bih_l, const float* __restrict__ bhh_l,
                                const float* __restrict__ bih_r, const float* __restrict__ bhh_r,
                                float* __restrict__ nxt, __nv_bfloat16* __restrict__ nxtbf)
{
    int row = blockIdx.x;
    const float* gp = gh  + (size_t)row * GH_LD;
    const float* hp = cur + (size_t)row * HH;
    size_t lo = (size_t)(2 * row) * HH;

    for (int j = threadIdx.x; j < HH; j += blockDim.x) {
        float hv = hp[j];
        // left GRU
        float g0 = gp[j], g1 = gp[HH + j], g2 = gp[2 * HH + j];
        float r  = sigmoidf_(bih_l[j]        + bhh_l[j]        + g0);
        float z  = sigmoidf_(bih_l[HH + j]   + bhh_l[HH + j]   + g1);
        float n  = tanhf   (bih_l[2*HH + j]  + r * (g2 + bhh_l[2*HH + j]));
        float left = (1.f - z) * n + z * hv;
        // right GRU
        g0 = gp[3*HH + j]; g1 = gp[4*HH + j]; g2 = gp[5*HH + j];
        float r2 = sigmoidf_(bih_r[j]        + bhh_r[j]        + g0);
        float z2 = sigmoidf_(bih_r[HH + j]   + bhh_r[HH + j]   + g1);
        float n2 = tanhf   (bih_r[2*HH + j]  + r2 * (g2 + bhh_r[2*HH + j]));
        float right = (1.f - z2) * n2 + z2 * hv;

        nxt[lo + j]        = left;
        nxt[lo + HH + j]   = right;
        nxtbf[lo + j]      = __float2bfloat16(left);
        nxtbf[lo + HH + j] = __float2bfloat16(right);
    }
}

// ---------------- streaming log-sum-exp per row (V=32000) ----------------
__global__ void lse_kernel(const float* __restrict__ logits, float* __restrict__ lse) {
    int row = blockIdx.x;
    const float4* p = reinterpret_cast<const float4*>(logits + (size_t)row * VV);
    float m = -INFINITY, s = 0.f;
    for (int i = threadIdx.x; i < VV / 4; i += blockDim.x) {
        float4 v = p[i];
        float x;
        x = v.x; if (x > m) { s *= __expf(m - x); m = x; } s += __expf(x - m);
        x = v.y; if (x > m) { s *= __expf(m - x); m = x; } s += __expf(x - m);
        x = v.z; if (x > m) { s *= __expf(m - x); m = x; } s += __expf(x - m);
        x = v.w; if (x > m) { s *= __expf(m - x); m = x; } s += __expf(x - m);
    }
    __shared__ float sm[256], ss[256];
    sm[threadIdx.x] = m; ss[threadIdx.x] = s;
    __syncthreads();
    for (int o = 128; o > 0; o >>= 1) {
        if (threadIdx.x < o) {
            float m2 = sm[threadIdx.x + o], s2 = ss[threadIdx.x + o];
            float M = fmaxf(sm[threadIdx.x], m2);
            ss[threadIdx.x] = ss[threadIdx.x] * __expf(sm[threadIdx.x] - M) + s2 * __expf(m2 - M);
            sm[threadIdx.x] = M;
        }
        __syncthreads();
    }
    if (threadIdx.x == 0) lse[row] = sm[0] + __logf(ss[0]);
}

__global__ void norm_kernel(float* __restrict__ logits, const float* __restrict__ lse) {
    int row = blockIdx.x;
    float l = lse[row];
    float4* p = reinterpret_cast<float4*>(logits + (size_t)row * VV);
    for (int i = threadIdx.x; i < VV / 4; i += blockDim.x) {
        float4 v = p[i];
        v.x -= l; v.y -= l; v.z -= l; v.w -= l;
        p[i] = v;
    }
}

// ---------------- launch ----------------
extern "C" void kernel_launch(void* const* d_in, const int* in_sizes, int n_in,
                              void* d_out, int out_size) {
    const float* enc   = (const float*)d_in[0];
    const float* Whh_l = (const float*)d_in[1];
    const float* bih_l = (const float*)d_in[2];
    const float* bhh_l = (const float*)d_in[3];
    const float* Whh_r = (const float*)d_in[4];
    const float* bih_r = (const float*)d_in[5];
    const float* bhh_r = (const float*)d_in[6];
    const float* W_out = (const float*)d_in[7];
    const float* b_out = (const float*)d_in[8];
    float* out = (float*)d_out;

    float *p_curA, *p_curB, *p_gh, *p_lse;
    __nv_bfloat16 *p_curbf, *p_wcat, *p_wout;
    cudaGetSymbolAddress((void**)&p_curA,  g_curA);
    cudaGetSymbolAddress((void**)&p_curB,  g_curB);
    cudaGetSymbolAddress((void**)&p_gh,    g_gh);
    cudaGetSymbolAddress((void**)&p_lse,   g_lse);
    cudaGetSymbolAddress((void**)&p_curbf, g_curbf);
    cudaGetSymbolAddress((void**)&p_wcat,  g_wcat);
    cudaGetSymbolAddress((void**)&p_wout,  g_wout);

    // weight conversions (every call — deterministic)
    {
        int nW = 3 * HH * HH;
        int n2 = nW / 2;
        f2bf_kernel<<<(n2 + 255) / 256, 256>>>(Whh_l, p_wcat, n2);
        f2bf_kernel<<<(n2 + 255) / 256, 256>>>(Whh_r, p_wcat + nW, n2);
        int n2o = (VV * HH) / 2;
        f2bf_kernel<<<(n2o + 255) / 256, 256>>>(W_out, p_wout, n2o);
    }

    // level 0 input
    init_kernel<<<(BB * HH) / 256, 256>>>(enc, p_curA, p_curbf);

    // tree expansion
    float* cur = p_curA;
    float* nxt = p_curB;
    for (int level = 0; level < DEPTHN; level++) {
        int rows = BB << level;                               // 64..1024
        dim3 grid(GH_LD / BN, (rows + BM - 1) / BM);
        gemm_bf16_pipe<<<grid, 256>>>(p_curbf, p_wcat, p_gh, nullptr, rows, GH_LD);
        gru_gate_kernel<<<rows, 256>>>(cur, p_gh, bih_l, bhh_l, bih_r, bhh_r, nxt, p_curbf);
        float* t = cur; cur = nxt; nxt = t;
    }

    // output projection: logits (+bias) straight into d_out
    {
        dim3 grid(VV / BN, MAXROWS / BM);                     // (250, 16)
        gemm_bf16_pipe<<<grid, 256>>>(p_curbf, p_wout, out, b_out, MAXROWS, VV);
    }

    // log_softmax
    lse_kernel<<<MAXROWS, 256>>>(out, p_lse);
    norm_kernel<<<MAXROWS, 256>>>(out, p_lse);
}

// round 9
// speedup vs baseline: 1.7472x; 1.1140x over previous
#include <cuda_runtime.h>
#include <cuda_bf16.h>
#include <math.h>

// Problem constants (fixed by the dataset)
#define BB   64
#define HH   1024
#define VV   32000
#define DEPTHN 5
#define LEAVES 32            // 2^DEPTH
#define MAXROWS (BB*LEAVES)  // 2048
#define GH_LD (6*HH)         // 6144 : [l gates 3H | r gates 3H]
#define NYB  (VV/128)        // 250 col-tiles in logits GEMM

// ---------------- device scratch (static, no runtime alloc) ----------------
__device__ float            g_curA[MAXROWS*HH];
__device__ float            g_curB[MAXROWS*HH];
__device__ __nv_bfloat16    g_curbf[MAXROWS*HH];
__device__ float            g_gh[(MAXROWS/2)*GH_LD];        // max 1024 rows * 6144
__device__ __nv_bfloat16    g_wcat[GH_LD*HH];               // [Whh_l ; Whh_r] (6144 x 1024)
__device__ __nv_bfloat16    g_wout[(size_t)VV*HH];          // 32000 x 1024
__device__ float            g_lse[MAXROWS];
__device__ float            g_pmax[MAXROWS*NYB];            // per-block row max partials
__device__ float            g_psum[MAXROWS*NYB];            // per-block row sumexp partials

// ---------------- helpers ----------------
__device__ __forceinline__ float sigmoidf_(float x) { return 1.f / (1.f + __expf(-x)); }

__device__ __forceinline__ void mma16816(float* c, const unsigned* a, const unsigned* b) {
    asm volatile(
        "mma.sync.aligned.m16n8k16.row.col.f32.bf16.bf16.f32 "
        "{%0,%1,%2,%3}, {%4,%5,%6,%7}, {%8,%9}, {%0,%1,%2,%3};\n"
        : "+f"(c[0]), "+f"(c[1]), "+f"(c[2]), "+f"(c[3])
        : "r"(a[0]), "r"(a[1]), "r"(a[2]), "r"(a[3]), "r"(b[0]), "r"(b[1]));
}

__device__ __forceinline__ void ldsm_x4(unsigned& r0, unsigned& r1, unsigned& r2, unsigned& r3,
                                        unsigned addr) {
    asm volatile("ldmatrix.sync.aligned.m8n8.x4.shared.b16 {%0,%1,%2,%3}, [%4];\n"
                 : "=r"(r0), "=r"(r1), "=r"(r2), "=r"(r3) : "r"(addr));
}

__device__ __forceinline__ void cp16(unsigned dst, const void* src, int szbytes) {
    asm volatile("cp.async.cg.shared.global [%0], [%1], 16, %2;\n"
                 :: "r"(dst), "l"(src), "r"(szbytes));
}
#define CP_COMMIT() asm volatile("cp.async.commit_group;\n" ::: "memory")
#define CP_WAIT(n)  asm volatile("cp.async.wait_group %0;\n" :: "n"(n) : "memory")

// online (max, sumexp) update
__device__ __forceinline__ void lse_upd(float& m, float& s, float x) {
    if (x > m) { s *= __expf(m - x); m = x; }
    s += __expf(x - m);
}
// combine two (m, s) pairs
__device__ __forceinline__ void lse_comb(float& m, float& s, float m2, float s2) {
    float M = fmaxf(m, m2);
    float ns = 0.f;
    if (M > -INFINITY) ns = s * __expf(m - M) + s2 * __expf(m2 - M);
    m = M; s = ns;
}

// ---------------- fp32 -> bf16 conversion ----------------
__global__ void f2bf_kernel(const float* __restrict__ src, __nv_bfloat16* __restrict__ dst, int n2) {
    int i = blockIdx.x * blockDim.x + threadIdx.x;
    if (i < n2) {
        float2 v = reinterpret_cast<const float2*>(src)[i];
        reinterpret_cast<__nv_bfloat162*>(dst)[i] = __float22bfloat162_rn(v);
    }
}

// ---------------- init: encoding -> curA (fp32) + curbf ----------------
__global__ void init_kernel(const float* __restrict__ enc, float* __restrict__ cur,
                            __nv_bfloat16* __restrict__ curbf) {
    int i = blockIdx.x * blockDim.x + threadIdx.x;
    float v = enc[i];
    cur[i]   = v;
    curbf[i] = __float2bfloat16(v);
}

// ---------------- pipelined bf16 GEMM:  C[M,N] = A[M,K] @ B[N,K]^T (+bias) ----------------
// K = 1024. BM=128, BN=128, BK=64, 2-stage cp.async (dynamic smem), ldmatrix fragments.
// grid: x = row tiles (for L2-friendly B reuse), y = col tiles.
// 256 threads, warp grid 4x2 (m x n), warp tile 32x64 -> 2x8 m16n8k16.
// Optional fused log-sum-exp partials per (row, col-block) when pmax != nullptr.
#define BM 128
#define BN 128
#define BK 64
#define KSTB 144                 // smem row stride in bytes (72 bf16) — conflict-free
#define STGB (BM*KSTB)           // bytes per A (or B) stage = 18432
#define SMEM_BYTES (4*STGB)      // 2 stages x (A+B) = 73728

__device__ __forceinline__ void stage_load(const __nv_bfloat16* __restrict__ A,
                                           const __nv_bfloat16* __restrict__ B,
                                           unsigned aS, unsigned bS,
                                           int rowBase, int M, int k0, int tid) {
    // A tile: 128x64 bf16 = 1024 x 16B chunks, 4 per thread
    #pragma unroll
    for (int i = 0; i < 4; i++) {
        int c  = tid + i * 256;
        int r  = c >> 3;                         // 0..127
        int cc = (c & 7) << 3;                   // bf16 col 0..56
        const __nv_bfloat16* src = A + (size_t)(rowBase + r) * HH + k0 + cc;
        int sz = (rowBase + r < M) ? 16 : 0;     // zero-fill OOB rows
        cp16(aS + r * KSTB + cc * 2, src, sz);
    }
    // B tile: 128x64, always in-range (B pre-offset by colBase)
    #pragma unroll
    for (int i = 0; i < 4; i++) {
        int c  = tid + i * 256;
        int r  = c >> 3;
        int cc = (c & 7) << 3;
        cp16(bS + r * KSTB + cc * 2, B + (size_t)r * HH + k0 + cc, 16);
    }
}

__global__ void __launch_bounds__(256, 2)
gemm_bf16_pipe(const __nv_bfloat16* __restrict__ A,
               const __nv_bfloat16* __restrict__ B,
               float* __restrict__ C,
               const float* __restrict__ bias,
               int M, int ldc,
               float* __restrict__ pmax, float* __restrict__ psum, int nyb)
{
    extern __shared__ char dynsm[];

    const int tid  = threadIdx.x;
    const int warp = tid >> 5;
    const int lane = tid & 31;
    const int wm   = warp >> 1;      // 0..3  (m)
    const int wn   = warp & 1;       // 0..1  (n)
    const int ti   = lane & 3;
    const int g    = lane >> 2;
    const int rowBase = blockIdx.x * BM;
    const int colBase = blockIdx.y * BN;

    const __nv_bfloat16* Bp = B + (size_t)colBase * HH;

    unsigned aB0 = (unsigned)__cvta_generic_to_shared(dynsm);
    unsigned bB0 = aB0 + 2 * STGB;

    float acc[2][8][4];
    #pragma unroll
    for (int mt = 0; mt < 2; mt++)
        #pragma unroll
        for (int nt = 0; nt < 8; nt++)
            #pragma unroll
            for (int q = 0; q < 4; q++) acc[mt][nt][q] = 0.f;

    const int NK = HH / BK;          // 16

    stage_load(A, Bp, aB0, bB0, rowBase, M, 0, tid);
    CP_COMMIT();

    const int aRowSel = lane & 15;
    const int aColSel = (lane >> 4) << 3;
    const int bRowSel = (lane & 7) + (((lane >> 4) & 1) << 3);
    const int bColSel = ((lane >> 3) & 1) << 3;

    for (int it = 0; it < NK; it++) {
        if (it + 1 < NK) {
            int s = (it + 1) & 1;
            stage_load(A, Bp, aB0 + s * STGB, bB0 + s * STGB, rowBase, M, (it + 1) * BK, tid);
            CP_COMMIT();
            CP_WAIT(1);
        } else {
            CP_WAIT(0);
        }
        __syncthreads();

        const int s = it & 1;
        const unsigned aS = aB0 + s * STGB;
        const unsigned bS = bB0 + s * STGB;

        #pragma unroll
        for (int kk = 0; kk < BK; kk += 16) {
            unsigned a[2][4], b[8][2];
            #pragma unroll
            for (int mt = 0; mt < 2; mt++) {
                int row = wm * 32 + mt * 16 + aRowSel;
                ldsm_x4(a[mt][0], a[mt][1], a[mt][2], a[mt][3],
                        aS + row * KSTB + (kk + aColSel) * 2);
            }
            #pragma unroll
            for (int p = 0; p < 4; p++) {
                int row = wn * 64 + p * 16 + bRowSel;
                unsigned r0, r1, r2, r3;
                ldsm_x4(r0, r1, r2, r3, bS + row * KSTB + (kk + bColSel) * 2);
                b[2*p][0] = r0; b[2*p][1] = r1; b[2*p+1][0] = r2; b[2*p+1][1] = r3;
            }
            #pragma unroll
            for (int mt = 0; mt < 2; mt++)
                #pragma unroll
                for (int nt = 0; nt < 8; nt++)
                    mma16816(acc[mt][nt], a[mt], b[nt]);
        }
        __syncthreads();
    }

    // ---- epilogue: bias add + store + optional per-row LSE partials
    float rm[2][2], rs[2][2];
    #pragma unroll
    for (int mt = 0; mt < 2; mt++)
        #pragma unroll
        for (int h = 0; h < 2; h++) { rm[mt][h] = -INFINITY; rs[mt][h] = 0.f; }

    #pragma unroll
    for (int mt = 0; mt < 2; mt++) {
        int r0 = rowBase + wm * 32 + mt * 16 + g;
        #pragma unroll
        for (int nt = 0; nt < 8; nt++) {
            int c = colBase + wn * 64 + nt * 8 + 2 * ti;
            float b0 = bias ? bias[c]     : 0.f;
            float b1 = bias ? bias[c + 1] : 0.f;
            float v0 = acc[mt][nt][0] + b0, v1 = acc[mt][nt][1] + b1;
            float v2 = acc[mt][nt][2] + b0, v3 = acc[mt][nt][3] + b1;
            if (r0 < M) {
                C[(size_t)r0 * ldc + c]     = v0;
                C[(size_t)r0 * ldc + c + 1] = v1;
            }
            if (r0 + 8 < M) {
                C[(size_t)(r0 + 8) * ldc + c]     = v2;
                C[(size_t)(r0 + 8) * ldc + c + 1] = v3;
            }
            if (pmax) {
                lse_upd(rm[mt][0], rs[mt][0], v0); lse_upd(rm[mt][0], rs[mt][0], v1);
                lse_upd(rm[mt][1], rs[mt][1], v2); lse_upd(rm[mt][1], rs[mt][1], v3);
            }
        }
    }

    if (pmax) {
        __shared__ float smx[BM][2], sms[BM][2];
        // reduce across ti (4 lanes share a row)
        #pragma unroll
        for (int mt = 0; mt < 2; mt++)
            #pragma unroll
            for (int h = 0; h < 2; h++) {
                #pragma unroll
                for (int o = 1; o <= 2; o <<= 1) {
                    float om = __shfl_xor_sync(0xffffffffu, rm[mt][h], o);
                    float os = __shfl_xor_sync(0xffffffffu, rs[mt][h], o);
                    lse_comb(rm[mt][h], rs[mt][h], om, os);
                }
            }
        if (ti == 0) {
            #pragma unroll
            for (int mt = 0; mt < 2; mt++)
                #pragma unroll
                for (int h = 0; h < 2; h++) {
                    int row = wm * 32 + mt * 16 + h * 8 + g;
                    smx[row][wn] = rm[mt][h];
                    sms[row][wn] = rs[mt][h];
                }
        }
        __syncthreads();
        if (tid < BM) {
            float m = smx[tid][0], s = sms[tid][0];
            lse_comb(m, s, smx[tid][1], sms[tid][1]);
            int grow = rowBase + tid;
            if (grow < M) {
                pmax[(size_t)grow * nyb + blockIdx.y] = m;
                psum[(size_t)grow * nyb + blockIdx.y] = s;
            }
        }
    }
}

// ---------------- GRU gates: consume gh (raw h@W^T), produce both children ----------------
__global__ void gru_gate_kernel(const float* __restrict__ cur,
                                const float* __restrict__ gh,
                                const float* __restrict__ bih_l, const float* __restrict__ bhh_l,
                                const float* __restrict__ bih_r, const float* __restrict__ bhh_r,
                                float* __restrict__ nxt, __nv_bfloat16* __restrict__ nxtbf)
{
    int row = blockIdx.x;
    const float* gp = gh  + (size_t)row * GH_LD;
    const float* hp = cur + (size_t)row * HH;
    size_t lo = (size_t)(2 * row) * HH;

    for (int j = threadIdx.x; j < HH; j += blockDim.x) {
        float hv = hp[j];
        // left GRU
        float g0 = gp[j], g1 = gp[HH + j], g2 = gp[2 * HH + j];
        float r  = sigmoidf_(bih_l[j]        + bhh_l[j]        + g0);
        float z  = sigmoidf_(bih_l[HH + j]   + bhh_l[HH + j]   + g1);
        float n  = tanhf   (bih_l[2*HH + j]  + r * (g2 + bhh_l[2*HH + j]));
        float left = (1.f - z) * n + z * hv;
        // right GRU
        g0 = gp[3*HH + j]; g1 = gp[4*HH + j]; g2 = gp[5*HH + j];
        float r2 = sigmoidf_(bih_r[j]        + bhh_r[j]        + g0);
        float z2 = sigmoidf_(bih_r[HH + j]   + bhh_r[HH + j]   + g1);
        float n2 = tanhf   (bih_r[2*HH + j]  + r2 * (g2 + bhh_r[2*HH + j]));
        float right = (1.f - z2) * n2 + z2 * hv;

        nxt[lo + j]        = left;
        nxt[lo + HH + j]   = right;
        nxtbf[lo + j]      = __float2bfloat16(left);
        nxtbf[lo + HH + j] = __float2bfloat16(right);
    }
}

// ---------------- finish LSE from per-block partials ----------------
__global__ void lse_finish_kernel(const float* __restrict__ pmax, const float* __restrict__ psum,
                                  float* __restrict__ lse, int nyb) {
    int row = blockIdx.x;
    float m = -INFINITY, s = 0.f;
    for (int i = threadIdx.x; i < nyb; i += blockDim.x)
        lse_comb(m, s, pmax[(size_t)row * nyb + i], psum[(size_t)row * nyb + i]);
    __shared__ float sm[256], ss[256];
    sm[threadIdx.x] = m; ss[threadIdx.x] = s;
    __syncthreads();
    for (int o = 128; o > 0; o >>= 1) {
        if (threadIdx.x < o) {
            float mm = sm[threadIdx.x], sv = ss[threadIdx.x];
            lse_comb(mm, sv, sm[threadIdx.x + o], ss[threadIdx.x + o]);
            sm[threadIdx.x] = mm; ss[threadIdx.x] = sv;
        }
        __syncthreads();
    }
    if (threadIdx.x == 0) lse[row] = sm[0] + __logf(ss[0]);
}

__global__ void norm_kernel(float* __restrict__ logits, const float* __restrict__ lse) {
    int row = blockIdx.x;
    float l = lse[row];
    float4* p = reinterpret_cast<float4*>(logits + (size_t)row * VV);
    for (int i = threadIdx.x; i < VV / 4; i += blockDim.x) {
        float4 v = p[i];
        v.x -= l; v.y -= l; v.z -= l; v.w -= l;
        p[i] = v;
    }
}

// ---------------- launch ----------------
extern "C" void kernel_launch(void* const* d_in, const int* in_sizes, int n_in,
                              void* d_out, int out_size) {
    const float* enc   = (const float*)d_in[0];
    const float* Whh_l = (const float*)d_in[1];
    const float* bih_l = (const float*)d_in[2];
    const float* bhh_l = (const float*)d_in[3];
    const float* Whh_r = (const float*)d_in[4];
    const float* bih_r = (const float*)d_in[5];
    const float* bhh_r = (const float*)d_in[6];
    const float* W_out = (const float*)d_in[7];
    const float* b_out = (const float*)d_in[8];
    float* out = (float*)d_out;

    float *p_curA, *p_curB, *p_gh, *p_lse, *p_pmax, *p_psum;
    __nv_bfloat16 *p_curbf, *p_wcat, *p_wout;
    cudaGetSymbolAddress((void**)&p_curA,  g_curA);
    cudaGetSymbolAddress((void**)&p_curB,  g_curB);
    cudaGetSymbolAddress((void**)&p_gh,    g_gh);
    cudaGetSymbolAddress((void**)&p_lse,   g_lse);
    cudaGetSymbolAddress((void**)&p_pmax,  g_pmax);
    cudaGetSymbolAddress((void**)&p_psum,  g_psum);
    cudaGetSymbolAddress((void**)&p_curbf, g_curbf);
    cudaGetSymbolAddress((void**)&p_wcat,  g_wcat);
    cudaGetSymbolAddress((void**)&p_wout,  g_wout);

    cudaFuncSetAttribute(gemm_bf16_pipe, cudaFuncAttributeMaxDynamicSharedMemorySize, SMEM_BYTES);

    // weight conversions (every call — deterministic)
    {
        int nW = 3 * HH * HH;
        int n2 = nW / 2;
        f2bf_kernel<<<(n2 + 255) / 256, 256>>>(Whh_l, p_wcat, n2);
        f2bf_kernel<<<(n2 + 255) / 256, 256>>>(Whh_r, p_wcat + nW, n2);
        int n2o = (VV * HH) / 2;
        f2bf_kernel<<<(n2o + 255) / 256, 256>>>(W_out, p_wout, n2o);
    }

    // level 0 input
    init_kernel<<<(BB * HH) / 256, 256>>>(enc, p_curA, p_curbf);

    // tree expansion
    float* cur = p_curA;
    float* nxt = p_curB;
    for (int level = 0; level < DEPTHN; level++) {
        int rows = BB << level;                               // 64..1024
        dim3 grid((rows + BM - 1) / BM, GH_LD / BN);          // x=rows, y=cols
        gemm_bf16_pipe<<<grid, 256, SMEM_BYTES>>>(p_curbf, p_wcat, p_gh, nullptr, rows, GH_LD,
                                                  nullptr, nullptr, 0);
        gru_gate_kernel<<<rows, 256>>>(cur, p_gh, bih_l, bhh_l, bih_r, bhh_r, nxt, p_curbf);
        float* t = cur; cur = nxt; nxt = t;
    }

    // output projection with fused LSE partials: logits (+bias) into d_out
    {
        dim3 grid(MAXROWS / BM, VV / BN);                     // (16, 250)
        gemm_bf16_pipe<<<grid, 256, SMEM_BYTES>>>(p_curbf, p_wout, out, b_out, MAXROWS, VV,
                                                  p_pmax, p_psum, NYB);
    }

    // log_softmax finish
    lse_finish_kernel<<<MAXROWS, 256>>>(p_pmax, p_psum, p_lse, NYB);
    norm_kernel<<<MAXROWS, 256>>>(out, p_lse);
}